// round 15
// baseline (speedup 1.0000x reference)
#include <cuda_runtime.h>
#include <cuda_bf16.h>
#include <mma.h>
#include <cstdint>

using namespace nvcuda;

#define NN 50000
#define EE 250000
#define EEP 250032   // +32 pad rows for tail-chunk fragment loads
#define NPAD 50048   // 391 * 128

// ---------------- persistent scratch ----------------
__device__ float g_x[(size_t)NPAD * 64];     // single buffer (in-place scatter-max)
__device__ float g_goal[16];
__device__ __nv_bfloat16 g_ybh[(size_t)EEP * 64];
__device__ __nv_bfloat16 g_ybl[(size_t)EEP * 64];
__device__ float g_P0[(size_t)NPAD * 64];    // fx node partials (seg0: x[src])
__device__ float g_P1[(size_t)NPAD * 64];    // fx node partials (seg1: x[dst])
__device__ float g_Q0[(size_t)NPAD * 64];    // fy node partials (seg0: x/vc[dst])
__device__ float g_Q1[(size_t)NPAD * 64];    // fy node partials (seg1: x/vc[src])
__device__ float g_why[18 * 64];
__device__ float g_whx[18 * 64];
__device__ float g_bhx[64];
// bf16 hi/lo folded weights, layout [seg][j(out 0..63)][k(0..63)]
__device__ __nv_bfloat16 g_bfx1h[3 * 64 * 64], g_bfx1l[3 * 64 * 64];
__device__ __nv_bfloat16 g_bfx2h[64 * 64],     g_bfx2l[64 * 64];
__device__ __nv_bfloat16 g_bfy1h[2 * 64 * 64], g_bfy1l[2 * 64 * 64];
__device__ __nv_bfloat16 g_bfy2h[64 * 64],     g_bfy2l[64 * 64];
__device__ __nv_bfloat16 g_bhy2h[64 * 64],     g_bhy2l[64 * 64];   // hy W2 (y0 init)

__device__ __forceinline__ void atomicMaxF(float* addr, float v) {
    if (v >= 0.f) atomicMax((int*)addr, __float_as_int(v));
    else          atomicMin((unsigned int*)addr, __float_as_uint(v));
}
// split 2 floats into packed bf16x2 hi + lo residual (a = low half of word)
__device__ __forceinline__ void split2(float a, float b, uint32_t& h, uint32_t& l) {
    asm("cvt.rn.bf16x2.f32 %0, %1, %2;" : "=r"(h) : "f"(b), "f"(a));
    float ha = __uint_as_float(h << 16);
    float hb = __uint_as_float(h & 0xFFFF0000u);
    float la = a - ha, lb = b - hb;
    asm("cvt.rn.bf16x2.f32 %0, %1, %2;" : "=r"(l) : "f"(lb), "f"(la));
}
#define BARP(id) asm volatile("bar.sync %0, 64;" :: "r"(id) : "memory")

// ---------------- goal ----------------
__global__ void k_goal(const float* __restrict__ v,
                       const float* __restrict__ labels, int n) {
    __shared__ float bv[1024];
    __shared__ int   bi[1024];
    float best = -1e30f; int bidx = 0;
    for (int i = threadIdx.x; i < n; i += 1024) {
        float val = labels[2 * i + 1];
        if (val > best) { best = val; bidx = i; }
    }
    bv[threadIdx.x] = best; bi[threadIdx.x] = bidx;
    __syncthreads();
    for (int s = 512; s > 0; s >>= 1) {
        if (threadIdx.x < s) {
            float ov = bv[threadIdx.x + s]; int oi = bi[threadIdx.x + s];
            if (ov > bv[threadIdx.x] || (ov == bv[threadIdx.x] && oi < bi[threadIdx.x])) {
                bv[threadIdx.x] = ov; bi[threadIdx.x] = oi;
            }
        }
        __syncthreads();
    }
    if (threadIdx.x == 0) {
        int g = bi[0];
        #pragma unroll
        for (int c = 0; c < 7; c++) g_goal[c] = v[g * 7 + c];
        g_goal[7] = labels[2 * g];
        g_goal[8] = labels[2 * g + 1];
    }
}

// ---------------- k_prep: all weight folds/transposes/splits in one launch ----
__global__ void k_prep(const float* __restrict__ hyw1,
                       const float* __restrict__ hxw1,
                       const float* __restrict__ hxb1,
                       const float* __restrict__ fxw1, const float* __restrict__ fxw2,
                       const float* __restrict__ fyw1, const float* __restrict__ fyw2,
                       const float* __restrict__ hyw2) {
    int idx = blockIdx.x * 256 + threadIdx.x;
    if (idx < 2368) {
        if (idx < 1152) {
            int k = idx >> 6, j = idx & 63;
            float o;
            if (k < 9) o = hyw1[k * 64 + j] + hyw1[(9 + k) * 64 + j];
            else       o = hyw1[(9 + k) * 64 + j] - hyw1[(k - 9) * 64 + j];
            g_why[idx] = o;
        } else if (idx < 2304) {
            int r = idx - 1152;
            int k = r >> 6, j = r & 63;
            float o;
            if (k < 9) o = hxw1[k * 64 + j] + hxw1[(18 + k) * 64 + j];
            else       o = hxw1[(18 + k) * 64 + j];
            g_whx[r] = o;
        } else {
            int j = idx - 2304;
            float acc = hxb1[j];
            #pragma unroll
            for (int c = 0; c < 9; c++)
                acc += g_goal[c] * (hxw1[(9 + c) * 64 + j] - hxw1[(18 + c) * 64 + j]);
            g_bhx[j] = acc;
        }
    } else if (idx < 18752) {
        int r2 = idx - 2368;
        if (r2 < 12288) {
            int seg = r2 >> 12, r = r2 & 4095, j = r >> 6, k = r & 63;
            int kg = seg * 64 + k;
            float c;
            if (kg < 64)       c = fxw1[(64 + kg) * 64 + j] + fxw1[kg * 64 + j];
            else if (kg < 128) c = fxw1[(64 + kg) * 64 + j] - fxw1[(kg - 64) * 64 + j];
            else               c = fxw1[(64 + kg) * 64 + j];
            __nv_bfloat16 h = __float2bfloat16(c);
            g_bfx1h[r2] = h;
            g_bfx1l[r2] = __float2bfloat16(c - __bfloat162float(h));
        } else {
            int r = r2 - 12288, j = r >> 6, k = r & 63;
            float c = fxw2[k * 64 + j];
            __nv_bfloat16 h = __float2bfloat16(c);
            g_bfx2h[r] = h;
            g_bfx2l[r] = __float2bfloat16(c - __bfloat162float(h));
        }
    } else if (idx < 35136) {
        int r2 = idx - 18752;
        if (r2 < 8192) {
            int seg = r2 >> 12, r = r2 & 4095, j = r >> 6, k = r & 63;
            int kg = seg * 64 + k;
            float c;
            if (kg < 64) c = fyw1[kg * 64 + j] + fyw1[(64 + kg) * 64 + j];
            else         c = fyw1[(64 + kg) * 64 + j] - fyw1[(kg - 64) * 64 + j];
            __nv_bfloat16 h = __float2bfloat16(c);
            g_bfy1h[r2] = h;
            g_bfy1l[r2] = __float2bfloat16(c - __bfloat162float(h));
        } else if (r2 < 12288) {
            int r = r2 - 8192, j = r >> 6, k = r & 63;
            float c = fyw2[k * 64 + j];
            __nv_bfloat16 h = __float2bfloat16(c);
            g_bfy2h[r] = h;
            g_bfy2l[r] = __float2bfloat16(c - __bfloat162float(h));
        } else {
            int r = r2 - 12288, j = r >> 6, k = r & 63;
            float c = hyw2[k * 64 + j];
            __nv_bfloat16 h = __float2bfloat16(c);
            g_bhy2h[r] = h;
            g_bhy2l[r] = __float2bfloat16(c - __bfloat162float(h));
        }
    }
}

// ---------------- k_initA: x0 (first nx blocks) + y0 node partials (rest) -----
__global__ __launch_bounds__(256) void k_initA(
        const float* __restrict__ v, const float* __restrict__ labels,
        const float* __restrict__ hxw2, const float* __restrict__ hxb2,
        int n, int nx) {
    if ((int)blockIdx.x < nx) {
        __shared__ float in_s[4][18];
        __shared__ float h_s[4][64];
        int g = threadIdx.x >> 6, j = threadIdx.x & 63;
        int node = blockIdx.x * 4 + g;
        if (j < 9) {
            float vc = (j < 7) ? v[node * 7 + j] : labels[node * 2 + (j - 7)];
            float d  = vc - g_goal[j];
            in_s[g][j]     = vc;
            in_s[g][9 + j] = d * d;
        }
        __syncthreads();
        {
            float acc = g_bhx[j];
            #pragma unroll
            for (int k = 0; k < 18; k++) acc = fmaf(in_s[g][k], g_whx[k * 64 + j], acc);
            h_s[g][j] = fmaxf(acc, 0.f);
        }
        __syncthreads();
        {
            float acc = hxb2[j];
            #pragma unroll
            for (int k = 0; k < 64; k++) acc = fmaf(h_s[g][k], hxw2[k * 64 + j], acc);
            g_x[(size_t)node * 64 + j] = acc;
        }
    } else {
        // Q0 = vc@Wvj, Q1 = vc@Wvi  (hoisted y0 node partials)
        __shared__ float vc_s[4][12];
        int g = threadIdx.x >> 6, j = threadIdx.x & 63;
        int node = ((int)blockIdx.x - nx) * 4 + g;
        if (j < 9) {
            float vc = (j < 7) ? v[node * 7 + j] : labels[node * 2 + (j - 7)];
            vc_s[g][j] = vc;
        }
        __syncthreads();
        float q0 = 0.f, q1 = 0.f;
        #pragma unroll
        for (int c = 0; c < 9; c++) {
            float sv = vc_s[g][c];
            q0 = fmaf(sv, g_why[c * 64 + j], q0);
            q1 = fmaf(sv, g_why[(9 + c) * 64 + j], q1);
        }
        g_Q0[(size_t)node * 64 + j] = q0;
        g_Q1[(size_t)node * 64 + j] = q1;
    }
}

// ---------------------------------------------------------------------------
// k_nodePB: from g_x compute fx partials P0/P1 (always) and fy partials
// Q0/Q1 (if do_fy). 128 nodes/block, 2 CTAs/SM.
// ---------------------------------------------------------------------------
__global__ __launch_bounds__(256, 2) void k_nodePB(int do_fy, int n) {
    extern __shared__ __align__(16) char smem[];
    __nv_bfloat16* Ah  = (__nv_bfloat16*)smem;               // 128 x 72
    __nv_bfloat16* Al  = (__nv_bfloat16*)(smem + 18432);
    __nv_bfloat16* WXH = (__nv_bfloat16*)(smem + 36864);     // 128 x 72 (fx segs)
    __nv_bfloat16* WXL = (__nv_bfloat16*)(smem + 55296);
    __nv_bfloat16* WYH = (__nv_bfloat16*)(smem + 73728);     // 128 x 72 (fy segs)
    __nv_bfloat16* WYL = (__nv_bfloat16*)(smem + 92160);     // total 110592
    int tid = threadIdx.x, wid = tid >> 5;

    for (int i = tid; i < 1024; i += 256) {     // 128 rows x 64 bf16 (uint4 = 8)
        int j = i >> 3, k8 = (i & 7) * 8;
        *(uint4*)&WXH[j * 72 + k8] = ((const uint4*)g_bfx1h)[i];
        *(uint4*)&WXL[j * 72 + k8] = ((const uint4*)g_bfx1l)[i];
        if (do_fy) {
            *(uint4*)&WYH[j * 72 + k8] = ((const uint4*)g_bfy1h)[i];
            *(uint4*)&WYL[j * 72 + k8] = ((const uint4*)g_bfy1l)[i];
        }
    }
    {
        int r = tid >> 1, half = tid & 1;
        int node = blockIdx.x * 128 + r;
        int ncl = node < n ? node : n - 1;
        const float4* xs = (const float4*)(g_x + (size_t)ncl * 64) + half * 8;
        #pragma unroll
        for (int i = 0; i < 8; i++) {
            float4 f = xs[i];
            uint32_t h0, l0, h1, l1;
            split2(f.x, f.y, h0, l0);
            split2(f.z, f.w, h1, l1);
            int c = half * 32 + i * 4;
            *(uint2*)&Ah[r * 72 + c] = make_uint2(h0, h1);
            *(uint2*)&Al[r * 72 + c] = make_uint2(l0, l1);
        }
    }
    __syncthreads();

    size_t ro = (size_t)(blockIdx.x * 128 + wid * 16) * 64;
    for (int pass = 0; pass < (do_fy ? 2 : 1); pass++) {
        const __nv_bfloat16* WH = pass ? WYH : WXH;
        const __nv_bfloat16* WL = pass ? WYL : WXL;
        float* D0 = pass ? g_Q0 : g_P0;
        float* D1 = pass ? g_Q1 : g_P1;
        wmma::fragment<wmma::accumulator, 16, 16, 16, float> acc0[4], acc1[4];
        #pragma unroll
        for (int t = 0; t < 4; t++) { wmma::fill_fragment(acc0[t], 0.f); wmma::fill_fragment(acc1[t], 0.f); }
        #pragma unroll
        for (int kt = 0; kt < 4; kt++) {
            wmma::fragment<wmma::matrix_a, 16, 16, 16, __nv_bfloat16, wmma::row_major> fah, fal;
            wmma::load_matrix_sync(fah, Ah + wid * 16 * 72 + kt * 16, 72);
            wmma::load_matrix_sync(fal, Al + wid * 16 * 72 + kt * 16, 72);
            #pragma unroll
            for (int t = 0; t < 4; t++) {
                wmma::fragment<wmma::matrix_b, 16, 16, 16, __nv_bfloat16, wmma::col_major> fbh, fbl;
                wmma::load_matrix_sync(fbh, WH + (t * 16) * 72 + kt * 16, 72);
                wmma::load_matrix_sync(fbl, WL + (t * 16) * 72 + kt * 16, 72);
                wmma::mma_sync(acc0[t], fah, fbh, acc0[t]);
                wmma::mma_sync(acc0[t], fah, fbl, acc0[t]);
                wmma::mma_sync(acc0[t], fal, fbh, acc0[t]);
                wmma::load_matrix_sync(fbh, WH + (64 + t * 16) * 72 + kt * 16, 72);
                wmma::load_matrix_sync(fbl, WL + (64 + t * 16) * 72 + kt * 16, 72);
                wmma::mma_sync(acc1[t], fah, fbh, acc1[t]);
                wmma::mma_sync(acc1[t], fah, fbl, acc1[t]);
                wmma::mma_sync(acc1[t], fal, fbh, acc1[t]);
            }
        }
        #pragma unroll
        for (int t = 0; t < 4; t++) {
            wmma::store_matrix_sync(D0 + ro + t * 16, acc0[t], 64, wmma::mem_row_major);
            wmma::store_matrix_sync(D1 + ro + t * 16, acc1[t], 64, wmma::mem_row_major);
        }
    }
}

// ---------------------------------------------------------------------------
// k_fx2: warp-pair 32-edge chunks (2m x 2n per warp), named pair barriers.
// GEMM1 A from global y mirrors; atomics snapshot-pruned; in-place into g_x.
// ---------------------------------------------------------------------------
__global__ __launch_bounds__(256, 2) void k_fx2(
        const int* __restrict__ ei,
        const float* __restrict__ b1, const float* __restrict__ b2,
        int ne, int nch) {
    extern __shared__ __align__(16) char smem[];
    __nv_bfloat16* HH  = (__nv_bfloat16*)(smem);             // 128 x 72
    __nv_bfloat16* HL  = (__nv_bfloat16*)(smem + 18432);
    float*         CS  = (float*)(smem + 36864);             // 128 x 72 f32
    __nv_bfloat16* W1H = (__nv_bfloat16*)(smem + 73728);     // 64 x 72
    __nv_bfloat16* W1L = (__nv_bfloat16*)(smem + 82944);
    __nv_bfloat16* W2H = (__nv_bfloat16*)(smem + 92160);
    __nv_bfloat16* W2L = (__nv_bfloat16*)(smem + 101376);    // total 110592

    int tid = threadIdx.x, wid = tid >> 5, lane = tid & 31;
    for (int i = tid; i < 512; i += 256) {
        int j = i >> 3, k8 = (i & 7) * 8;
        *(uint4*)&W1H[j * 72 + k8] = ((const uint4*)(g_bfx1h + 8192))[i];   // seg2 (y)
        *(uint4*)&W1L[j * 72 + k8] = ((const uint4*)(g_bfx1l + 8192))[i];
        *(uint4*)&W2H[j * 72 + k8] = ((const uint4*)g_bfx2h)[i];
        *(uint4*)&W2L[j * 72 + k8] = ((const uint4*)g_bfx2l)[i];
    }
    __syncthreads();

    int pair = wid >> 1, side = wid & 1, c0 = side * 32;
    int rbase = pair * 32;
    int bid = 1 + pair;
    const float4* b1v = (const float4*)(b1 + c0);
    const float4* b2v = (const float4*)(b2 + c0);

    for (int ch = blockIdx.x * 4 + pair; ch < nch; ch += gridDim.x * 4) {
        int e = ch * 32 + lane;
        int ec = e < ne ? e : ne - 1;
        int s = ei[ec], d = ei[ne + ec];
        int row = rbase + lane;
        {   // GEMM1: C = y @ W1y  (A from global mirrors)
            wmma::fragment<wmma::accumulator, 16, 16, 16, float> acc[2][2];
            #pragma unroll
            for (int m = 0; m < 2; m++)
                #pragma unroll
                for (int t = 0; t < 2; t++) wmma::fill_fragment(acc[m][t], 0.f);
            size_t ar = (size_t)ch * 2048;
            #pragma unroll
            for (int kt = 0; kt < 4; kt++) {
                wmma::fragment<wmma::matrix_a, 16, 16, 16, __nv_bfloat16, wmma::row_major> fa0h, fa0l, fa1h, fa1l;
                wmma::load_matrix_sync(fa0h, g_ybh + ar + kt * 16, 64);
                wmma::load_matrix_sync(fa0l, g_ybl + ar + kt * 16, 64);
                wmma::load_matrix_sync(fa1h, g_ybh + ar + 1024 + kt * 16, 64);
                wmma::load_matrix_sync(fa1l, g_ybl + ar + 1024 + kt * 16, 64);
                #pragma unroll
                for (int t = 0; t < 2; t++) {
                    wmma::fragment<wmma::matrix_b, 16, 16, 16, __nv_bfloat16, wmma::col_major> fbh, fbl;
                    wmma::load_matrix_sync(fbh, W1H + (c0 + t * 16) * 72 + kt * 16, 72);
                    wmma::load_matrix_sync(fbl, W1L + (c0 + t * 16) * 72 + kt * 16, 72);
                    wmma::mma_sync(acc[0][t], fa0h, fbh, acc[0][t]);
                    wmma::mma_sync(acc[0][t], fa0h, fbl, acc[0][t]);
                    wmma::mma_sync(acc[0][t], fa0l, fbh, acc[0][t]);
                    wmma::mma_sync(acc[1][t], fa1h, fbh, acc[1][t]);
                    wmma::mma_sync(acc[1][t], fa1h, fbl, acc[1][t]);
                    wmma::mma_sync(acc[1][t], fa1l, fbh, acc[1][t]);
                }
            }
            #pragma unroll
            for (int m = 0; m < 2; m++)
                #pragma unroll
                for (int t = 0; t < 2; t++)
                    wmma::store_matrix_sync(CS + (rbase + m * 16) * 72 + c0 + t * 16,
                                            acc[m][t], 72, wmma::mem_row_major);
        }
        __syncwarp();
        {   // ep1: H = relu(C + P0[s] + P1[d] + b1)  (own cols of own row)
            const float*  Crow = CS + row * 72 + c0;
            __nv_bfloat16* hh  = HH + row * 72 + c0;
            __nv_bfloat16* hl  = HL + row * 72 + c0;
            const float4* ps = (const float4*)(g_P0 + (size_t)s * 64 + c0);
            const float4* pd = (const float4*)(g_P1 + (size_t)d * 64 + c0);
            #pragma unroll
            for (int i = 0; i < 8; i++) {
                float4 cv = ((const float4*)Crow)[i];
                float4 av = ps[i], bv = pd[i], biv = b1v[i];
                float f0 = fmaxf(cv.x + av.x + bv.x + biv.x, 0.f);
                float f1 = fmaxf(cv.y + av.y + bv.y + biv.y, 0.f);
                float f2 = fmaxf(cv.z + av.z + bv.z + biv.z, 0.f);
                float f3 = fmaxf(cv.w + av.w + bv.w + biv.w, 0.f);
                uint32_t h0, l0, h1, l1;
                split2(f0, f1, h0, l0);
                split2(f2, f3, h1, l1);
                *(uint2*)&hh[i * 4] = make_uint2(h0, h1);
                *(uint2*)&hl[i * 4] = make_uint2(l0, l1);
            }
        }
        BARP(bid);
        {   // GEMM2: C = H @ W2
            wmma::fragment<wmma::accumulator, 16, 16, 16, float> acc[2][2];
            #pragma unroll
            for (int m = 0; m < 2; m++)
                #pragma unroll
                for (int t = 0; t < 2; t++) wmma::fill_fragment(acc[m][t], 0.f);
            #pragma unroll
            for (int kt = 0; kt < 4; kt++) {
                wmma::fragment<wmma::matrix_a, 16, 16, 16, __nv_bfloat16, wmma::row_major> fa0h, fa0l, fa1h, fa1l;
                wmma::load_matrix_sync(fa0h, HH + rbase * 72 + kt * 16, 72);
                wmma::load_matrix_sync(fa0l, HL + rbase * 72 + kt * 16, 72);
                wmma::load_matrix_sync(fa1h, HH + (rbase + 16) * 72 + kt * 16, 72);
                wmma::load_matrix_sync(fa1l, HL + (rbase + 16) * 72 + kt * 16, 72);
                #pragma unroll
                for (int t = 0; t < 2; t++) {
                    wmma::fragment<wmma::matrix_b, 16, 16, 16, __nv_bfloat16, wmma::col_major> fbh, fbl;
                    wmma::load_matrix_sync(fbh, W2H + (c0 + t * 16) * 72 + kt * 16, 72);
                    wmma::load_matrix_sync(fbl, W2L + (c0 + t * 16) * 72 + kt * 16, 72);
                    wmma::mma_sync(acc[0][t], fa0h, fbh, acc[0][t]);
                    wmma::mma_sync(acc[0][t], fa0h, fbl, acc[0][t]);
                    wmma::mma_sync(acc[0][t], fa0l, fbh, acc[0][t]);
                    wmma::mma_sync(acc[1][t], fa1h, fbh, acc[1][t]);
                    wmma::mma_sync(acc[1][t], fa1h, fbl, acc[1][t]);
                    wmma::mma_sync(acc[1][t], fa1l, fbh, acc[1][t]);
                }
            }
            #pragma unroll
            for (int m = 0; m < 2; m++)
                #pragma unroll
                for (int t = 0; t < 2; t++)
                    wmma::store_matrix_sync(CS + (rbase + m * 16) * 72 + c0 + t * 16,
                                            acc[m][t], 72, wmma::mem_row_major);
        }
        __syncwarp();
        if (e < ne) {   // ep2: scatter-max (snapshot-pruned)
            const float* Crow = CS + row * 72 + c0;
            float* dp = g_x + (size_t)d * 64 + c0;
            #pragma unroll
            for (int i = 0; i < 8; i++) {
                float4 cv  = ((const float4*)Crow)[i];
                float4 biv = b2v[i];
                float4 cur = *(const float4*)(dp + i * 4);
                float m0 = cv.x + biv.x, m1 = cv.y + biv.y;
                float m2 = cv.z + biv.z, m3 = cv.w + biv.w;
                if (m0 > cur.x) atomicMaxF(dp + i * 4 + 0, m0);
                if (m1 > cur.y) atomicMaxF(dp + i * 4 + 1, m1);
                if (m2 > cur.z) atomicMaxF(dp + i * 4 + 2, m2);
                if (m3 > cur.w) atomicMaxF(dp + i * 4 + 3, m3);
            }
        }
        BARP(bid);
    }
}

// ---------------------------------------------------------------------------
// k_fy2: warp-pair 32-edge chunks. H = relu(Q0[d]+Q1[s]+b1); y' = H@W2 + b2;
// init=0: y = max(mirror, y'); init=1: y = y'. Mirrors only.
// ---------------------------------------------------------------------------
__global__ __launch_bounds__(256, 2) void k_fy2(
        const int* __restrict__ ei,
        const float* __restrict__ b1, const float* __restrict__ b2,
        int ne, int nch, int sel, int init) {
    extern __shared__ __align__(16) char smem[];
    __nv_bfloat16* HH  = (__nv_bfloat16*)(smem);
    __nv_bfloat16* HL  = (__nv_bfloat16*)(smem + 18432);
    float*         CS  = (float*)(smem + 36864);
    __nv_bfloat16* W2H = (__nv_bfloat16*)(smem + 73728);
    __nv_bfloat16* W2L = (__nv_bfloat16*)(smem + 82944);     // total 92160

    int tid = threadIdx.x, wid = tid >> 5, lane = tid & 31;
    {
        const uint4* w2h_g = sel ? (const uint4*)g_bhy2h : (const uint4*)g_bfy2h;
        const uint4* w2l_g = sel ? (const uint4*)g_bhy2l : (const uint4*)g_bfy2l;
        for (int i = tid; i < 512; i += 256) {
            int j = i >> 3, k8 = (i & 7) * 8;
            *(uint4*)&W2H[j * 72 + k8] = w2h_g[i];
            *(uint4*)&W2L[j * 72 + k8] = w2l_g[i];
        }
    }
    __syncthreads();

    int pair = wid >> 1, side = wid & 1, c0 = side * 32;
    int rbase = pair * 32;
    int bid = 1 + pair;
    const float4* b1v = (const float4*)(b1 + c0);
    const float4* b2v = (const float4*)(b2 + c0);

    for (int ch = blockIdx.x * 4 + pair; ch < nch; ch += gridDim.x * 4) {
        int e = ch * 32 + lane;
        int ec = e < ne ? e : ne - 1;
        int s = ei[ec], d = ei[ne + ec];
        int row = rbase + lane;
        {   // ep1: H = relu(Q0[d] + Q1[s] + b1)
            __nv_bfloat16* hh = HH + row * 72 + c0;
            __nv_bfloat16* hl = HL + row * 72 + c0;
            const float4* pj = (const float4*)(g_Q0 + (size_t)d * 64 + c0);
            const float4* pi = (const float4*)(g_Q1 + (size_t)s * 64 + c0);
            #pragma unroll
            for (int i = 0; i < 8; i++) {
                float4 av = pj[i], bv = pi[i], biv = b1v[i];
                float f0 = fmaxf(av.x + bv.x + biv.x, 0.f);
                float f1 = fmaxf(av.y + bv.y + biv.y, 0.f);
                float f2 = fmaxf(av.z + bv.z + biv.z, 0.f);
                float f3 = fmaxf(av.w + bv.w + biv.w, 0.f);
                uint32_t h0, l0, h1, l1;
                split2(f0, f1, h0, l0);
                split2(f2, f3, h1, l1);
                *(uint2*)&hh[i * 4] = make_uint2(h0, h1);
                *(uint2*)&hl[i * 4] = make_uint2(l0, l1);
            }
        }
        BARP(bid);
        {   // GEMM: C = H @ W2
            wmma::fragment<wmma::accumulator, 16, 16, 16, float> acc[2][2];
            #pragma unroll
            for (int m = 0; m < 2; m++)
                #pragma unroll
                for (int t = 0; t < 2; t++) wmma::fill_fragment(acc[m][t], 0.f);
            #pragma unroll
            for (int kt = 0; kt < 4; kt++) {
                wmma::fragment<wmma::matrix_a, 16, 16, 16, __nv_bfloat16, wmma::row_major> fa0h, fa0l, fa1h, fa1l;
                wmma::load_matrix_sync(fa0h, HH + rbase * 72 + kt * 16, 72);
                wmma::load_matrix_sync(fa0l, HL + rbase * 72 + kt * 16, 72);
                wmma::load_matrix_sync(fa1h, HH + (rbase + 16) * 72 + kt * 16, 72);
                wmma::load_matrix_sync(fa1l, HL + (rbase + 16) * 72 + kt * 16, 72);
                #pragma unroll
                for (int t = 0; t < 2; t++) {
                    wmma::fragment<wmma::matrix_b, 16, 16, 16, __nv_bfloat16, wmma::col_major> fbh, fbl;
                    wmma::load_matrix_sync(fbh, W2H + (c0 + t * 16) * 72 + kt * 16, 72);
                    wmma::load_matrix_sync(fbl, W2L + (c0 + t * 16) * 72 + kt * 16, 72);
                    wmma::mma_sync(acc[0][t], fa0h, fbh, acc[0][t]);
                    wmma::mma_sync(acc[0][t], fa0h, fbl, acc[0][t]);
                    wmma::mma_sync(acc[0][t], fa0l, fbh, acc[0][t]);
                    wmma::mma_sync(acc[1][t], fa1h, fbh, acc[1][t]);
                    wmma::mma_sync(acc[1][t], fa1h, fbl, acc[1][t]);
                    wmma::mma_sync(acc[1][t], fa1l, fbh, acc[1][t]);
                }
            }
            #pragma unroll
            for (int m = 0; m < 2; m++)
                #pragma unroll
                for (int t = 0; t < 2; t++)
                    wmma::store_matrix_sync(CS + (rbase + m * 16) * 72 + c0 + t * 16,
                                            acc[m][t], 72, wmma::mem_row_major);
        }
        __syncwarp();
        if (e < ne) {   // ep2: y = max(old, C+b2) -> mirrors
            const float* Crow = CS + row * 72 + c0;
            uint32_t* mh = (uint32_t*)(g_ybh + (size_t)e * 64 + c0);
            uint32_t* ml = (uint32_t*)(g_ybl + (size_t)e * 64 + c0);
            #pragma unroll
            for (int i = 0; i < 8; i++) {
                float4 cv  = ((const float4*)Crow)[i];
                float4 biv = b2v[i];
                float y0 = cv.x + biv.x, y1 = cv.y + biv.y;
                float y2 = cv.z + biv.z, y3 = cv.w + biv.w;
                if (!init) {
                    uint2 hw = *(uint2*)&mh[2 * i];
                    uint2 lw = *(uint2*)&ml[2 * i];
                    y0 = fmaxf(y0, __uint_as_float(hw.x << 16)         + __uint_as_float(lw.x << 16));
                    y1 = fmaxf(y1, __uint_as_float(hw.x & 0xFFFF0000u) + __uint_as_float(lw.x & 0xFFFF0000u));
                    y2 = fmaxf(y2, __uint_as_float(hw.y << 16)         + __uint_as_float(lw.y << 16));
                    y3 = fmaxf(y3, __uint_as_float(hw.y & 0xFFFF0000u) + __uint_as_float(lw.y & 0xFFFF0000u));
                }
                uint32_t h0, l0, h1, l1;
                split2(y0, y1, h0, l0);
                split2(y2, y3, h1, l1);
                *(uint2*)&mh[2 * i] = make_uint2(h0, h1);
                *(uint2*)&ml[2 * i] = make_uint2(l0, l1);
            }
        }
        BARP(bid);
    }
}

// ---------------- head ----------------
__global__ __launch_bounds__(256) void k_out(
        const float* __restrict__ w1, const float* __restrict__ b1,
        const float* __restrict__ w2, const float* __restrict__ b2,
        const float* __restrict__ w3, float* __restrict__ out, int n) {
    __shared__ float x_s[16][68];
    __shared__ float h_s[16][68];
    int g = threadIdx.x >> 4, tt = threadIdx.x & 15;
    int node = blockIdx.x * 16 + g;
    *(float4*)(&x_s[g][4 * tt]) = *(const float4*)(g_x + (size_t)node * 64 + 4 * tt);
    __syncthreads();
    const float4* w1v = (const float4*)w1;
    float4 acc = *(const float4*)(b1 + 4 * tt);
    #pragma unroll 8
    for (int k = 0; k < 64; k++) {
        float sv = x_s[g][k];
        float4 w = w1v[k * 16 + tt];
        acc.x = fmaf(sv, w.x, acc.x);
        acc.y = fmaf(sv, w.y, acc.y);
        acc.z = fmaf(sv, w.z, acc.z);
        acc.w = fmaf(sv, w.w, acc.w);
    }
    *(float4*)(&h_s[g][4 * tt]) = make_float4(fmaxf(acc.x, 0.f), fmaxf(acc.y, 0.f),
                                              fmaxf(acc.z, 0.f), fmaxf(acc.w, 0.f));
    __syncthreads();
    const float4* w2v = (const float4*)w2;
    float4 o = *(const float4*)(b2 + 4 * tt);
    #pragma unroll 8
    for (int k = 0; k < 64; k++) {
        float sv = h_s[g][k];
        float4 w = w2v[k * 16 + tt];
        o.x = fmaf(sv, w.x, o.x);
        o.y = fmaf(sv, w.y, o.y);
        o.z = fmaf(sv, w.z, o.z);
        o.w = fmaf(sv, w.w, o.w);
    }
    float4 w3v = *(const float4*)(w3 + 4 * tt);
    float p = fmaxf(o.x, 0.f) * w3v.x + fmaxf(o.y, 0.f) * w3v.y
            + fmaxf(o.z, 0.f) * w3v.z + fmaxf(o.w, 0.f) * w3v.w;
    #pragma unroll
    for (int sh = 8; sh > 0; sh >>= 1)
        p += __shfl_xor_sync(0xffffffffu, p, sh, 16);
    if (tt == 0) out[node] = p;
}

// ---------------------------------------------------------------------------
extern "C" void kernel_launch(void* const* d_in, const int* in_sizes, int n_in,
                              void* d_out, int out_size) {
    const float* v      = (const float*)d_in[0];
    const float* labels = (const float*)d_in[1];
    const int*   ei     = (const int*)d_in[2];
    const float *hx_w1 = (const float*)d_in[4],  *hx_b1 = (const float*)d_in[5];
    const float *hx_w2 = (const float*)d_in[6],  *hx_b2 = (const float*)d_in[7];
    const float *hy_w1 = (const float*)d_in[8],  *hy_b1 = (const float*)d_in[9];
    const float *hy_w2 = (const float*)d_in[10], *hy_b2 = (const float*)d_in[11];
    const float *fx_w1 = (const float*)d_in[12], *fx_b1 = (const float*)d_in[13];
    const float *fx_w2 = (const float*)d_in[14], *fx_b2 = (const float*)d_in[15];
    const float *fy_w1 = (const float*)d_in[16], *fy_b1 = (const float*)d_in[17];
    const float *fy_w2 = (const float*)d_in[18], *fy_b2 = (const float*)d_in[19];
    const float *fe_w1 = (const float*)d_in[20], *fe_b1 = (const float*)d_in[21];
    const float *fe_w2 = (const float*)d_in[22], *fe_b2 = (const float*)d_in[23];
    const float *fe_w3 = (const float*)d_in[24];

    int n  = in_sizes[0] / 7;       // 50000
    int ne = in_sizes[2] / 2;       // 250000
    float* out = (float*)d_out;

    const int SM_NP = 110592, SM_FX = 110592, SM_FY = 92160;
    cudaFuncSetAttribute((const void*)k_nodePB,
                         cudaFuncAttributeMaxDynamicSharedMemorySize, SM_NP);
    cudaFuncSetAttribute((const void*)k_fx2,
                         cudaFuncAttributeMaxDynamicSharedMemorySize, SM_FX);
    cudaFuncSetAttribute((const void*)k_fy2,
                         cudaFuncAttributeMaxDynamicSharedMemorySize, SM_FY);

    int nx  = n / 4;
    int nq  = n / 4;
    int npb = NPAD / 128;            // 391
    int nch = (ne + 31) / 32;        // 7813 (32-edge chunks)
    const int GRID = 296;

    k_goal<<<1, 1024>>>(v, labels, n);
    k_prep<<<138, 256>>>(hy_w1, hx_w1, hx_b1, fx_w1, fx_w2, fy_w1, fy_w2, hy_w2);
    k_initA<<<nx + nq, 256>>>(v, labels, hx_w2, hx_b2, n, nx);
    // y0 via hoisted partials (sel=1: hy W2, init=1: no max) -> mirrors
    k_fy2<<<GRID, 256, SM_FY>>>(ei, hy_b1, hy_b2, ne, nch, 1, 1);

    // iter 1
    k_nodePB<<<npb, 256, SM_NP>>>(0, n);
    k_fx2<<<GRID, 256, SM_FX>>>(ei, fx_b1, fx_b2, ne, nch);
    // iter 2
    k_nodePB<<<npb, 256, SM_NP>>>(1, n);
    k_fy2<<<GRID, 256, SM_FY>>>(ei, fy_b1, fy_b2, ne, nch, 0, 0);
    k_fx2<<<GRID, 256, SM_FX>>>(ei, fx_b1, fx_b2, ne, nch);
    // iter 3
    k_nodePB<<<npb, 256, SM_NP>>>(1, n);
    k_fy2<<<GRID, 256, SM_FY>>>(ei, fy_b1, fy_b2, ne, nch, 0, 0);
    k_fx2<<<GRID, 256, SM_FX>>>(ei, fx_b1, fx_b2, ne, nch);
    // iter-3 y update is dead code — dropped

    k_out<<<n / 16, 256>>>(fe_w1, fe_b1, fe_w2, fe_b2, fe_w3, out, n);
}

// round 17
// speedup vs baseline: 1.4278x; 1.4278x over previous
#include <cuda_runtime.h>
#include <cuda_bf16.h>
#include <mma.h>
#include <cstdint>

using namespace nvcuda;

#define NN 50000
#define EE 250000
#define NPAD 50048   // 391 * 128

// ---------------- persistent scratch ----------------
__device__ float g_x[(size_t)NPAD * 64];     // single buffer (in-place scatter-max)
__device__ float g_goal[16];
__device__ __nv_bfloat16 g_ybh[(size_t)EE * 64];
__device__ __nv_bfloat16 g_ybl[(size_t)EE * 64];
__device__ float g_P0[(size_t)NPAD * 64];    // fx node partials (seg0: x[src])
__device__ float g_P1[(size_t)NPAD * 64];    // fx node partials (seg1: x[dst])
__device__ float g_Q0[(size_t)NPAD * 64];    // fy node partials (seg0: x/vc[dst])
__device__ float g_Q1[(size_t)NPAD * 64];    // fy node partials (seg1: x/vc[src])
__device__ float g_why[18 * 64];
__device__ float g_whx[18 * 64];
__device__ float g_bhx[64];
// bf16 hi/lo folded weights, layout [seg][j(out 0..63)][k(0..63)]
__device__ __nv_bfloat16 g_bfx1h[3 * 64 * 64], g_bfx1l[3 * 64 * 64];
__device__ __nv_bfloat16 g_bfx2h[64 * 64],     g_bfx2l[64 * 64];
__device__ __nv_bfloat16 g_bfy1h[2 * 64 * 64], g_bfy1l[2 * 64 * 64];
__device__ __nv_bfloat16 g_bfy2h[64 * 64],     g_bfy2l[64 * 64];
__device__ __nv_bfloat16 g_bhy2h[64 * 64],     g_bhy2l[64 * 64];   // hy W2 (y0 init)

__device__ __forceinline__ void atomicMaxF(float* addr, float v) {
    if (v >= 0.f) atomicMax((int*)addr, __float_as_int(v));
    else          atomicMin((unsigned int*)addr, __float_as_uint(v));
}
// split 2 floats into packed bf16x2 hi + lo residual (a = low half of word)
__device__ __forceinline__ void split2(float a, float b, uint32_t& h, uint32_t& l) {
    asm("cvt.rn.bf16x2.f32 %0, %1, %2;" : "=r"(h) : "f"(b), "f"(a));
    float ha = __uint_as_float(h << 16);
    float hb = __uint_as_float(h & 0xFFFF0000u);
    float la = a - ha, lb = b - hb;
    asm("cvt.rn.bf16x2.f32 %0, %1, %2;" : "=r"(l) : "f"(lb), "f"(la));
}

// ---------------- goal ----------------
__global__ void k_goal(const float* __restrict__ v,
                       const float* __restrict__ labels, int n) {
    __shared__ float bv[1024];
    __shared__ int   bi[1024];
    float best = -1e30f; int bidx = 0;
    for (int i = threadIdx.x; i < n; i += 1024) {
        float val = labels[2 * i + 1];
        if (val > best) { best = val; bidx = i; }
    }
    bv[threadIdx.x] = best; bi[threadIdx.x] = bidx;
    __syncthreads();
    for (int s = 512; s > 0; s >>= 1) {
        if (threadIdx.x < s) {
            float ov = bv[threadIdx.x + s]; int oi = bi[threadIdx.x + s];
            if (ov > bv[threadIdx.x] || (ov == bv[threadIdx.x] && oi < bi[threadIdx.x])) {
                bv[threadIdx.x] = ov; bi[threadIdx.x] = oi;
            }
        }
        __syncthreads();
    }
    if (threadIdx.x == 0) {
        int g = bi[0];
        #pragma unroll
        for (int c = 0; c < 7; c++) g_goal[c] = v[g * 7 + c];
        g_goal[7] = labels[2 * g];
        g_goal[8] = labels[2 * g + 1];
    }
}

// ---------------- k_prep: all weight folds/transposes/splits in one launch ----
__global__ void k_prep(const float* __restrict__ hyw1,
                       const float* __restrict__ hxw1,
                       const float* __restrict__ hxb1,
                       const float* __restrict__ fxw1, const float* __restrict__ fxw2,
                       const float* __restrict__ fyw1, const float* __restrict__ fyw2,
                       const float* __restrict__ hyw2) {
    int idx = blockIdx.x * 256 + threadIdx.x;
    if (idx < 2368) {
        if (idx < 1152) {
            int k = idx >> 6, j = idx & 63;
            float o;
            if (k < 9) o = hyw1[k * 64 + j] + hyw1[(9 + k) * 64 + j];
            else       o = hyw1[(9 + k) * 64 + j] - hyw1[(k - 9) * 64 + j];
            g_why[idx] = o;
        } else if (idx < 2304) {
            int r = idx - 1152;
            int k = r >> 6, j = r & 63;
            float o;
            if (k < 9) o = hxw1[k * 64 + j] + hxw1[(18 + k) * 64 + j];
            else       o = hxw1[(18 + k) * 64 + j];
            g_whx[r] = o;
        } else {
            int j = idx - 2304;
            float acc = hxb1[j];
            #pragma unroll
            for (int c = 0; c < 9; c++)
                acc += g_goal[c] * (hxw1[(9 + c) * 64 + j] - hxw1[(18 + c) * 64 + j]);
            g_bhx[j] = acc;
        }
    } else if (idx < 18752) {
        int r2 = idx - 2368;
        if (r2 < 12288) {
            int seg = r2 >> 12, r = r2 & 4095, j = r >> 6, k = r & 63;
            int kg = seg * 64 + k;
            float c;
            if (kg < 64)       c = fxw1[(64 + kg) * 64 + j] + fxw1[kg * 64 + j];
            else if (kg < 128) c = fxw1[(64 + kg) * 64 + j] - fxw1[(kg - 64) * 64 + j];
            else               c = fxw1[(64 + kg) * 64 + j];
            __nv_bfloat16 h = __float2bfloat16(c);
            g_bfx1h[r2] = h;
            g_bfx1l[r2] = __float2bfloat16(c - __bfloat162float(h));
        } else {
            int r = r2 - 12288, j = r >> 6, k = r & 63;
            float c = fxw2[k * 64 + j];
            __nv_bfloat16 h = __float2bfloat16(c);
            g_bfx2h[r] = h;
            g_bfx2l[r] = __float2bfloat16(c - __bfloat162float(h));
        }
    } else if (idx < 35136) {
        int r2 = idx - 18752;
        if (r2 < 8192) {
            int seg = r2 >> 12, r = r2 & 4095, j = r >> 6, k = r & 63;
            int kg = seg * 64 + k;
            float c;
            if (kg < 64) c = fyw1[kg * 64 + j] + fyw1[(64 + kg) * 64 + j];
            else         c = fyw1[(64 + kg) * 64 + j] - fyw1[(kg - 64) * 64 + j];
            __nv_bfloat16 h = __float2bfloat16(c);
            g_bfy1h[r2] = h;
            g_bfy1l[r2] = __float2bfloat16(c - __bfloat162float(h));
        } else if (r2 < 12288) {
            int r = r2 - 8192, j = r >> 6, k = r & 63;
            float c = fyw2[k * 64 + j];
            __nv_bfloat16 h = __float2bfloat16(c);
            g_bfy2h[r] = h;
            g_bfy2l[r] = __float2bfloat16(c - __bfloat162float(h));
        } else {
            int r = r2 - 12288, j = r >> 6, k = r & 63;
            float c = hyw2[k * 64 + j];
            __nv_bfloat16 h = __float2bfloat16(c);
            g_bhy2h[r] = h;
            g_bhy2l[r] = __float2bfloat16(c - __bfloat162float(h));
        }
    }
}

// ---------------- k_initA: x0 (first nx blocks) + y0 node partials (rest) -----
__global__ __launch_bounds__(256) void k_initA(
        const float* __restrict__ v, const float* __restrict__ labels,
        const float* __restrict__ hxw2, const float* __restrict__ hxb2,
        int n, int nx) {
    if ((int)blockIdx.x < nx) {
        __shared__ float in_s[4][18];
        __shared__ float h_s[4][64];
        int g = threadIdx.x >> 6, j = threadIdx.x & 63;
        int node = blockIdx.x * 4 + g;
        if (j < 9) {
            float vc = (j < 7) ? v[node * 7 + j] : labels[node * 2 + (j - 7)];
            float d  = vc - g_goal[j];
            in_s[g][j]     = vc;
            in_s[g][9 + j] = d * d;
        }
        __syncthreads();
        {
            float acc = g_bhx[j];
            #pragma unroll
            for (int k = 0; k < 18; k++) acc = fmaf(in_s[g][k], g_whx[k * 64 + j], acc);
            h_s[g][j] = fmaxf(acc, 0.f);
        }
        __syncthreads();
        {
            float acc = hxb2[j];
            #pragma unroll
            for (int k = 0; k < 64; k++) acc = fmaf(h_s[g][k], hxw2[k * 64 + j], acc);
            g_x[(size_t)node * 64 + j] = acc;
        }
    } else {
        // Q0 = vc@Wvj, Q1 = vc@Wvi  (hoisted y0 node partials)
        __shared__ float vc_s[4][12];
        int g = threadIdx.x >> 6, j = threadIdx.x & 63;
        int node = ((int)blockIdx.x - nx) * 4 + g;
        if (j < 9) {
            float vc = (j < 7) ? v[node * 7 + j] : labels[node * 2 + (j - 7)];
            vc_s[g][j] = vc;
        }
        __syncthreads();
        float q0 = 0.f, q1 = 0.f;
        #pragma unroll
        for (int c = 0; c < 9; c++) {
            float sv = vc_s[g][c];
            q0 = fmaf(sv, g_why[c * 64 + j], q0);
            q1 = fmaf(sv, g_why[(9 + c) * 64 + j], q1);
        }
        g_Q0[(size_t)node * 64 + j] = q0;
        g_Q1[(size_t)node * 64 + j] = q1;
    }
}

// ---------------------------------------------------------------------------
// k_nodePB: from g_x compute fx partials P0/P1 (always) and fy partials
// Q0/Q1 (if do_fy). 128 nodes/block, 2 CTAs/SM.
// ---------------------------------------------------------------------------
__global__ __launch_bounds__(256, 2) void k_nodePB(int do_fy, int n) {
    extern __shared__ __align__(16) char smem[];
    __nv_bfloat16* Ah  = (__nv_bfloat16*)smem;               // 128 x 72
    __nv_bfloat16* Al  = (__nv_bfloat16*)(smem + 18432);
    __nv_bfloat16* WXH = (__nv_bfloat16*)(smem + 36864);     // 128 x 72 (fx segs)
    __nv_bfloat16* WXL = (__nv_bfloat16*)(smem + 55296);
    __nv_bfloat16* WYH = (__nv_bfloat16*)(smem + 73728);     // 128 x 72 (fy segs)
    __nv_bfloat16* WYL = (__nv_bfloat16*)(smem + 92160);     // total 110592
    int tid = threadIdx.x, wid = tid >> 5;

    for (int i = tid; i < 1024; i += 256) {     // 128 rows x 64 bf16 (uint4 = 8)
        int j = i >> 3, k8 = (i & 7) * 8;
        *(uint4*)&WXH[j * 72 + k8] = ((const uint4*)g_bfx1h)[i];
        *(uint4*)&WXL[j * 72 + k8] = ((const uint4*)g_bfx1l)[i];
        if (do_fy) {
            *(uint4*)&WYH[j * 72 + k8] = ((const uint4*)g_bfy1h)[i];
            *(uint4*)&WYL[j * 72 + k8] = ((const uint4*)g_bfy1l)[i];
        }
    }
    {
        int r = tid >> 1, half = tid & 1;
        int node = blockIdx.x * 128 + r;
        int ncl = node < n ? node : n - 1;
        const float4* xs = (const float4*)(g_x + (size_t)ncl * 64) + half * 8;
        #pragma unroll
        for (int i = 0; i < 8; i++) {
            float4 f = xs[i];
            uint32_t h0, l0, h1, l1;
            split2(f.x, f.y, h0, l0);
            split2(f.z, f.w, h1, l1);
            int c = half * 32 + i * 4;
            *(uint2*)&Ah[r * 72 + c] = make_uint2(h0, h1);
            *(uint2*)&Al[r * 72 + c] = make_uint2(l0, l1);
        }
    }
    __syncthreads();

    size_t ro = (size_t)(blockIdx.x * 128 + wid * 16) * 64;
    for (int pass = 0; pass < (do_fy ? 2 : 1); pass++) {
        const __nv_bfloat16* WH = pass ? WYH : WXH;
        const __nv_bfloat16* WL = pass ? WYL : WXL;
        float* D0 = pass ? g_Q0 : g_P0;
        float* D1 = pass ? g_Q1 : g_P1;
        wmma::fragment<wmma::accumulator, 16, 16, 16, float> acc0[4], acc1[4];
        #pragma unroll
        for (int t = 0; t < 4; t++) { wmma::fill_fragment(acc0[t], 0.f); wmma::fill_fragment(acc1[t], 0.f); }
        #pragma unroll
        for (int kt = 0; kt < 4; kt++) {
            wmma::fragment<wmma::matrix_a, 16, 16, 16, __nv_bfloat16, wmma::row_major> fah, fal;
            wmma::load_matrix_sync(fah, Ah + wid * 16 * 72 + kt * 16, 72);
            wmma::load_matrix_sync(fal, Al + wid * 16 * 72 + kt * 16, 72);
            #pragma unroll
            for (int t = 0; t < 4; t++) {
                wmma::fragment<wmma::matrix_b, 16, 16, 16, __nv_bfloat16, wmma::col_major> fbh, fbl;
                wmma::load_matrix_sync(fbh, WH + (t * 16) * 72 + kt * 16, 72);
                wmma::load_matrix_sync(fbl, WL + (t * 16) * 72 + kt * 16, 72);
                wmma::mma_sync(acc0[t], fah, fbh, acc0[t]);
                wmma::mma_sync(acc0[t], fah, fbl, acc0[t]);
                wmma::mma_sync(acc0[t], fal, fbh, acc0[t]);
                wmma::load_matrix_sync(fbh, WH + (64 + t * 16) * 72 + kt * 16, 72);
                wmma::load_matrix_sync(fbl, WL + (64 + t * 16) * 72 + kt * 16, 72);
                wmma::mma_sync(acc1[t], fah, fbh, acc1[t]);
                wmma::mma_sync(acc1[t], fah, fbl, acc1[t]);
                wmma::mma_sync(acc1[t], fal, fbh, acc1[t]);
            }
        }
        #pragma unroll
        for (int t = 0; t < 4; t++) {
            wmma::store_matrix_sync(D0 + ro + t * 16, acc0[t], 64, wmma::mem_row_major);
            wmma::store_matrix_sync(D1 + ro + t * 16, acc1[t], 64, wmma::mem_row_major);
        }
    }
}

// ---------------------------------------------------------------------------
// k_fx2: per-warp independent 16-edge chunks (round-14 verified version).
// ---------------------------------------------------------------------------
__global__ __launch_bounds__(256, 2) void k_fx2(
        const int* __restrict__ ei,
        const float* __restrict__ b1, const float* __restrict__ b2,
        int ne, int nch) {
    extern __shared__ __align__(16) char smem[];
    __nv_bfloat16* HH  = (__nv_bfloat16*)(smem);             // 128 x 72
    __nv_bfloat16* HL  = (__nv_bfloat16*)(smem + 18432);
    float*         CS  = (float*)(smem + 36864);             // 128 x 72 f32
    __nv_bfloat16* W1H = (__nv_bfloat16*)(smem + 73728);     // 64 x 72
    __nv_bfloat16* W1L = (__nv_bfloat16*)(smem + 82944);
    __nv_bfloat16* W2H = (__nv_bfloat16*)(smem + 92160);
    __nv_bfloat16* W2L = (__nv_bfloat16*)(smem + 101376);    // total 110592

    int tid = threadIdx.x, wid = tid >> 5, lane = tid & 31;
    for (int i = tid; i < 512; i += 256) {
        int j = i >> 3, k8 = (i & 7) * 8;
        *(uint4*)&W1H[j * 72 + k8] = ((const uint4*)(g_bfx1h + 8192))[i];   // seg2 (y)
        *(uint4*)&W1L[j * 72 + k8] = ((const uint4*)(g_bfx1l + 8192))[i];
        *(uint4*)&W2H[j * 72 + k8] = ((const uint4*)g_bfx2h)[i];
        *(uint4*)&W2L[j * 72 + k8] = ((const uint4*)g_bfx2l)[i];
    }
    __syncthreads();

    int er = lane >> 1, half = lane & 1, c0 = half * 32;
    int row = wid * 16 + er;
    float*         Crow = CS + row * 72 + c0;
    __nv_bfloat16* hh   = HH + row * 72 + c0;
    __nv_bfloat16* hl   = HL + row * 72 + c0;
    const float4* b1v = (const float4*)(b1 + c0);
    const float4* b2v = (const float4*)(b2 + c0);

    for (int ch = blockIdx.x * 8 + wid; ch < nch; ch += gridDim.x * 8) {
        int e0 = ch * 16;
        wmma::fragment<wmma::accumulator, 16, 16, 16, float> acc[4];
        #pragma unroll
        for (int t = 0; t < 4; t++) wmma::fill_fragment(acc[t], 0.f);
        #pragma unroll
        for (int kt = 0; kt < 4; kt++) {
            wmma::fragment<wmma::matrix_a, 16, 16, 16, __nv_bfloat16, wmma::row_major> fah, fal;
            wmma::load_matrix_sync(fah, g_ybh + (size_t)e0 * 64 + kt * 16, 64);
            wmma::load_matrix_sync(fal, g_ybl + (size_t)e0 * 64 + kt * 16, 64);
            #pragma unroll
            for (int t = 0; t < 4; t++) {
                wmma::fragment<wmma::matrix_b, 16, 16, 16, __nv_bfloat16, wmma::col_major> fbh, fbl;
                wmma::load_matrix_sync(fbh, W1H + (t * 16) * 72 + kt * 16, 72);
                wmma::load_matrix_sync(fbl, W1L + (t * 16) * 72 + kt * 16, 72);
                wmma::mma_sync(acc[t], fah, fbh, acc[t]);
                wmma::mma_sync(acc[t], fah, fbl, acc[t]);
                wmma::mma_sync(acc[t], fal, fbh, acc[t]);
            }
        }
        #pragma unroll
        for (int t = 0; t < 4; t++)
            wmma::store_matrix_sync(CS + (wid * 16) * 72 + t * 16, acc[t], 72, wmma::mem_row_major);
        __syncwarp();

        int e = e0 + er;
        int s = ei[e], d = ei[ne + e];
        {
            const float4* ps = (const float4*)(g_P0 + (size_t)s * 64 + c0);
            const float4* pd = (const float4*)(g_P1 + (size_t)d * 64 + c0);
            #pragma unroll
            for (int i = 0; i < 8; i++) {
                float4 cv = ((const float4*)Crow)[i];
                float4 av = ps[i], bv = pd[i], biv = b1v[i];
                float f0 = fmaxf(cv.x + av.x + bv.x + biv.x, 0.f);
                float f1 = fmaxf(cv.y + av.y + bv.y + biv.y, 0.f);
                float f2 = fmaxf(cv.z + av.z + bv.z + biv.z, 0.f);
                float f3 = fmaxf(cv.w + av.w + bv.w + biv.w, 0.f);
                uint32_t h0, l0, h1, l1;
                split2(f0, f1, h0, l0);
                split2(f2, f3, h1, l1);
                *(uint2*)&hh[i * 4] = make_uint2(h0, h1);
                *(uint2*)&hl[i * 4] = make_uint2(l0, l1);
            }
        }
        __syncwarp();
        #pragma unroll
        for (int t = 0; t < 4; t++) wmma::fill_fragment(acc[t], 0.f);
        #pragma unroll
        for (int kt = 0; kt < 4; kt++) {
            wmma::fragment<wmma::matrix_a, 16, 16, 16, __nv_bfloat16, wmma::row_major> fah, fal;
            wmma::load_matrix_sync(fah, HH + (wid * 16) * 72 + kt * 16, 72);
            wmma::load_matrix_sync(fal, HL + (wid * 16) * 72 + kt * 16, 72);
            #pragma unroll
            for (int t = 0; t < 4; t++) {
                wmma::fragment<wmma::matrix_b, 16, 16, 16, __nv_bfloat16, wmma::col_major> fbh, fbl;
                wmma::load_matrix_sync(fbh, W2H + (t * 16) * 72 + kt * 16, 72);
                wmma::load_matrix_sync(fbl, W2L + (t * 16) * 72 + kt * 16, 72);
                wmma::mma_sync(acc[t], fah, fbh, acc[t]);
                wmma::mma_sync(acc[t], fah, fbl, acc[t]);
                wmma::mma_sync(acc[t], fal, fbh, acc[t]);
            }
        }
        #pragma unroll
        for (int t = 0; t < 4; t++)
            wmma::store_matrix_sync(CS + (wid * 16) * 72 + t * 16, acc[t], 72, wmma::mem_row_major);
        __syncwarp();
        {
            float* dp = g_x + (size_t)d * 64 + c0;
            #pragma unroll
            for (int i = 0; i < 8; i++) {
                float4 cv  = ((const float4*)Crow)[i];
                float4 biv = b2v[i];
                float4 cur = *(const float4*)(dp + i * 4);   // monotone snapshot
                float m0 = cv.x + biv.x, m1 = cv.y + biv.y;
                float m2 = cv.z + biv.z, m3 = cv.w + biv.w;
                if (m0 > cur.x) atomicMaxF(dp + i * 4 + 0, m0);
                if (m1 > cur.y) atomicMaxF(dp + i * 4 + 1, m1);
                if (m2 > cur.z) atomicMaxF(dp + i * 4 + 2, m2);
                if (m3 > cur.w) atomicMaxF(dp + i * 4 + 3, m3);
            }
        }
        __syncwarp();
    }
}

// ---------------------------------------------------------------------------
// k_fy2: coalesced-gather version (FIXED: stage full 64-col rows).
//  stage: SQ = Q0[d_r] + Q1[s_r], 8 lanes/row x 2 float4 = full row, coalesced
//  ep1:   H = relu(SQ + b1) -> HH/HL
//  GEMM:  C = H @ W2 (overwrites CS after SQ consumed; same-warp program order)
//  ep2:   linear-coalesced mirror update: y = max(old, C + b2)
// ---------------------------------------------------------------------------
__global__ __launch_bounds__(256, 2) void k_fy2(
        const int* __restrict__ ei,
        const float* __restrict__ b1, const float* __restrict__ b2,
        int ne, int nch, int sel, int init) {
    extern __shared__ __align__(16) char smem[];
    __nv_bfloat16* HH  = (__nv_bfloat16*)(smem);
    __nv_bfloat16* HL  = (__nv_bfloat16*)(smem + 18432);
    float*         CS  = (float*)(smem + 36864);
    __nv_bfloat16* W2H = (__nv_bfloat16*)(smem + 73728);
    __nv_bfloat16* W2L = (__nv_bfloat16*)(smem + 82944);     // total 92160

    int tid = threadIdx.x, wid = tid >> 5, lane = tid & 31;
    {
        const uint4* w2h_g = sel ? (const uint4*)g_bhy2h : (const uint4*)g_bfy2h;
        const uint4* w2l_g = sel ? (const uint4*)g_bhy2l : (const uint4*)g_bfy2l;
        for (int i = tid; i < 512; i += 256) {
            int j = i >> 3, k8 = (i & 7) * 8;
            *(uint4*)&W2H[j * 72 + k8] = w2h_g[i];
            *(uint4*)&W2L[j * 72 + k8] = w2l_g[i];
        }
    }
    __syncthreads();

    int er = lane >> 1, half = lane & 1, c0 = half * 32;
    int rbase = wid * 16;
    float* SQ = CS + rbase * 72;            // per-warp staging (overlaid on own CS rows)
    __nv_bfloat16* hh = HH + (rbase + er) * 72 + c0;
    __nv_bfloat16* hl = HL + (rbase + er) * 72 + c0;
    const float4* b1v = (const float4*)(b1 + c0);
    // stage-load mapping: 8 lanes per row, 4 rows per instruction, 2 float4/lane
    int srow = lane >> 3, scol = (lane & 7) * 4;

    for (int ch = blockIdx.x * 8 + wid; ch < nch; ch += gridDim.x * 8) {
        int e0 = ch * 16;
        // indices for this warp's 16 edges (lanes 0-15 hold them)
        int sv = 0, dv = 0;
        if (lane < 16) { sv = ei[e0 + lane]; dv = ei[ne + e0 + lane]; }
        __syncwarp();
        {   // stage SQ = Q0[d_r] + Q1[s_r]  (full 64-col rows, coalesced)
            #pragma unroll
            for (int j = 0; j < 4; j++) {
                int r = j * 4 + srow;
                int dr = __shfl_sync(0xffffffffu, dv, r);
                int sr = __shfl_sync(0xffffffffu, sv, r);
                const float* q0p = g_Q0 + (size_t)dr * 64;
                const float* q1p = g_Q1 + (size_t)sr * 64;
                float4 qa = *(const float4*)(q0p + scol);
                float4 pa = *(const float4*)(q1p + scol);
                float4 qb = *(const float4*)(q0p + 32 + scol);
                float4 pb = *(const float4*)(q1p + 32 + scol);
                *(float4*)(SQ + r * 72 + scol) =
                    make_float4(qa.x + pa.x, qa.y + pa.y, qa.z + pa.z, qa.w + pa.w);
                *(float4*)(SQ + r * 72 + 32 + scol) =
                    make_float4(qb.x + pb.x, qb.y + pb.y, qb.z + pb.z, qb.w + pb.w);
            }
        }
        __syncwarp();
        {   // ep1: H = relu(SQ + b1)
            const float* sq = SQ + er * 72 + c0;
            #pragma unroll
            for (int i = 0; i < 8; i++) {
                float4 av = ((const float4*)sq)[i];
                float4 biv = b1v[i];
                float f0 = fmaxf(av.x + biv.x, 0.f);
                float f1 = fmaxf(av.y + biv.y, 0.f);
                float f2 = fmaxf(av.z + biv.z, 0.f);
                float f3 = fmaxf(av.w + biv.w, 0.f);
                uint32_t h0, l0, h1, l1;
                split2(f0, f1, h0, l0);
                split2(f2, f3, h1, l1);
                *(uint2*)&hh[i * 4] = make_uint2(h0, h1);
                *(uint2*)&hl[i * 4] = make_uint2(l0, l1);
            }
        }
        __syncwarp();
        {   // GEMM: C = H @ W2  (CS overwrite is after SQ consumed — same warp)
            wmma::fragment<wmma::accumulator, 16, 16, 16, float> acc[4];
            #pragma unroll
            for (int t = 0; t < 4; t++) wmma::fill_fragment(acc[t], 0.f);
            #pragma unroll
            for (int kt = 0; kt < 4; kt++) {
                wmma::fragment<wmma::matrix_a, 16, 16, 16, __nv_bfloat16, wmma::row_major> fah, fal;
                wmma::load_matrix_sync(fah, HH + rbase * 72 + kt * 16, 72);
                wmma::load_matrix_sync(fal, HL + rbase * 72 + kt * 16, 72);
                #pragma unroll
                for (int t = 0; t < 4; t++) {
                    wmma::fragment<wmma::matrix_b, 16, 16, 16, __nv_bfloat16, wmma::col_major> fbh, fbl;
                    wmma::load_matrix_sync(fbh, W2H + (t * 16) * 72 + kt * 16, 72);
                    wmma::load_matrix_sync(fbl, W2L + (t * 16) * 72 + kt * 16, 72);
                    wmma::mma_sync(acc[t], fah, fbh, acc[t]);
                    wmma::mma_sync(acc[t], fah, fbl, acc[t]);
                    wmma::mma_sync(acc[t], fal, fbh, acc[t]);
                }
            }
            #pragma unroll
            for (int t = 0; t < 4; t++)
                wmma::store_matrix_sync(CS + rbase * 72 + t * 16, acc[t], 72, wmma::mem_row_major);
        }
        __syncwarp();
        {   // ep2: linear-coalesced mirror update (y = max(old, C+b2))
            uint2* mh = (uint2*)(g_ybh + (size_t)e0 * 64);
            uint2* ml = (uint2*)(g_ybl + (size_t)e0 * 64);
            #pragma unroll
            for (int j = 0; j < 8; j++) {
                int t0 = j * 128 + lane * 4;         // linear elem in 16x64 block
                int r = t0 >> 6, col = t0 & 63;
                const float* cr = CS + (rbase + r) * 72 + col;
                float v0 = cr[0] + __ldg(b2 + col);
                float v1 = cr[1] + __ldg(b2 + col + 1);
                float v2 = cr[2] + __ldg(b2 + col + 2);
                float v3 = cr[3] + __ldg(b2 + col + 3);
                int widx = j * 32 + lane;            // uint2 index (coalesced)
                if (!init) {
                    uint2 hw = mh[widx];
                    uint2 lw = ml[widx];
                    v0 = fmaxf(v0, __uint_as_float(hw.x << 16)         + __uint_as_float(lw.x << 16));
                    v1 = fmaxf(v1, __uint_as_float(hw.x & 0xFFFF0000u) + __uint_as_float(lw.x & 0xFFFF0000u));
                    v2 = fmaxf(v2, __uint_as_float(hw.y << 16)         + __uint_as_float(lw.y << 16));
                    v3 = fmaxf(v3, __uint_as_float(hw.y & 0xFFFF0000u) + __uint_as_float(lw.y & 0xFFFF0000u));
                }
                uint32_t h0, l0, h1, l1;
                split2(v0, v1, h0, l0);
                split2(v2, v3, h1, l1);
                mh[widx] = make_uint2(h0, h1);
                ml[widx] = make_uint2(l0, l1);
            }
        }
        __syncwarp();
    }
}

// ---------------- head ----------------
__global__ __launch_bounds__(256) void k_out(
        const float* __restrict__ w1, const float* __restrict__ b1,
        const float* __restrict__ w2, const float* __restrict__ b2,
        const float* __restrict__ w3, float* __restrict__ out, int n) {
    __shared__ float x_s[16][68];
    __shared__ float h_s[16][68];
    int g = threadIdx.x >> 4, tt = threadIdx.x & 15;
    int node = blockIdx.x * 16 + g;
    *(float4*)(&x_s[g][4 * tt]) = *(const float4*)(g_x + (size_t)node * 64 + 4 * tt);
    __syncthreads();
    const float4* w1v = (const float4*)w1;
    float4 acc = *(const float4*)(b1 + 4 * tt);
    #pragma unroll 8
    for (int k = 0; k < 64; k++) {
        float sv = x_s[g][k];
        float4 w = w1v[k * 16 + tt];
        acc.x = fmaf(sv, w.x, acc.x);
        acc.y = fmaf(sv, w.y, acc.y);
        acc.z = fmaf(sv, w.z, acc.z);
        acc.w = fmaf(sv, w.w, acc.w);
    }
    *(float4*)(&h_s[g][4 * tt]) = make_float4(fmaxf(acc.x, 0.f), fmaxf(acc.y, 0.f),
                                              fmaxf(acc.z, 0.f), fmaxf(acc.w, 0.f));
    __syncthreads();
    const float4* w2v = (const float4*)w2;
    float4 o = *(const float4*)(b2 + 4 * tt);
    #pragma unroll 8
    for (int k = 0; k < 64; k++) {
        float sv = h_s[g][k];
        float4 w = w2v[k * 16 + tt];
        o.x = fmaf(sv, w.x, o.x);
        o.y = fmaf(sv, w.y, o.y);
        o.z = fmaf(sv, w.z, o.z);
        o.w = fmaf(sv, w.w, o.w);
    }
    float4 w3v = *(const float4*)(w3 + 4 * tt);
    float p = fmaxf(o.x, 0.f) * w3v.x + fmaxf(o.y, 0.f) * w3v.y
            + fmaxf(o.z, 0.f) * w3v.z + fmaxf(o.w, 0.f) * w3v.w;
    #pragma unroll
    for (int sh = 8; sh > 0; sh >>= 1)
        p += __shfl_xor_sync(0xffffffffu, p, sh, 16);
    if (tt == 0) out[node] = p;
}

// ---------------------------------------------------------------------------
extern "C" void kernel_launch(void* const* d_in, const int* in_sizes, int n_in,
                              void* d_out, int out_size) {
    const float* v      = (const float*)d_in[0];
    const float* labels = (const float*)d_in[1];
    const int*   ei     = (const int*)d_in[2];
    const float *hx_w1 = (const float*)d_in[4],  *hx_b1 = (const float*)d_in[5];
    const float *hx_w2 = (const float*)d_in[6],  *hx_b2 = (const float*)d_in[7];
    const float *hy_w1 = (const float*)d_in[8],  *hy_b1 = (const float*)d_in[9];
    const float *hy_w2 = (const float*)d_in[10], *hy_b2 = (const float*)d_in[11];
    const float *fx_w1 = (const float*)d_in[12], *fx_b1 = (const float*)d_in[13];
    const float *fx_w2 = (const float*)d_in[14], *fx_b2 = (const float*)d_in[15];
    const float *fy_w1 = (const float*)d_in[16], *fy_b1 = (const float*)d_in[17];
    const float *fy_w2 = (const float*)d_in[18], *fy_b2 = (const float*)d_in[19];
    const float *fe_w1 = (const float*)d_in[20], *fe_b1 = (const float*)d_in[21];
    const float *fe_w2 = (const float*)d_in[22], *fe_b2 = (const float*)d_in[23];
    const float *fe_w3 = (const float*)d_in[24];

    int n  = in_sizes[0] / 7;       // 50000
    int ne = in_sizes[2] / 2;       // 250000
    float* out = (float*)d_out;

    const int SM_NP = 110592, SM_FX = 110592, SM_FY = 92160;
    cudaFuncSetAttribute((const void*)k_nodePB,
                         cudaFuncAttributeMaxDynamicSharedMemorySize, SM_NP);
    cudaFuncSetAttribute((const void*)k_fx2,
                         cudaFuncAttributeMaxDynamicSharedMemorySize, SM_FX);
    cudaFuncSetAttribute((const void*)k_fy2,
                         cudaFuncAttributeMaxDynamicSharedMemorySize, SM_FY);

    int nx  = n / 4;
    int nq  = n / 4;
    int npb = NPAD / 128;            // 391
    int nch = ne / 16;               // 15625
    const int GRID = 296;

    k_goal<<<1, 1024>>>(v, labels, n);
    k_prep<<<138, 256>>>(hy_w1, hx_w1, hx_b1, fx_w1, fx_w2, fy_w1, fy_w2, hy_w2);
    k_initA<<<nx + nq, 256>>>(v, labels, hx_w2, hx_b2, n, nx);
    // y0 via hoisted partials (sel=1: hy W2, init=1: no max) -> mirrors
    k_fy2<<<GRID, 256, SM_FY>>>(ei, hy_b1, hy_b2, ne, nch, 1, 1);

    // iter 1
    k_nodePB<<<npb, 256, SM_NP>>>(0, n);
    k_fx2<<<GRID, 256, SM_FX>>>(ei, fx_b1, fx_b2, ne, nch);
    // iter 2
    k_nodePB<<<npb, 256, SM_NP>>>(1, n);
    k_fy2<<<GRID, 256, SM_FY>>>(ei, fy_b1, fy_b2, ne, nch, 0, 0);
    k_fx2<<<GRID, 256, SM_FX>>>(ei, fx_b1, fx_b2, ne, nch);
    // iter 3
    k_nodePB<<<npb, 256, SM_NP>>>(1, n);
    k_fy2<<<GRID, 256, SM_FY>>>(ei, fy_b1, fy_b2, ne, nch, 0, 0);
    k_fx2<<<GRID, 256, SM_FX>>>(ei, fx_b1, fx_b2, ne, nch);
    // iter-3 y update is dead code — dropped

    k_out<<<n / 16, 256>>>(fe_w1, fe_b1, fe_w2, fe_b2, fe_w3, out, n);
}